// round 1
// baseline (speedup 1.0000x reference)
#include <cuda_runtime.h>
#include <math.h>

#define B_  8
#define L_  1024
#define DM  512
#define DI  1024
#define DS  16
#define RK  32
#define NL  4

// ---------------- scratch (static device globals: allocation-guard safe) ----
__device__ float g_x  [B_*L_*DM];     // residual stream
__device__ float g_xn [B_*L_*DM];     // rmsnorm output
__device__ float g_uz [B_*L_*2*DI];   // in_proj output (u | z)
__device__ float g_u  [B_*L_*DI];     // conv+silu output
__device__ float g_dbc[B_*L_*64];     // x_proj output (dt_low | B | C)
__device__ float g_dt [B_*L_*DI];     // softplus(dt)
__device__ float g_y  [B_*L_*DI];     // scan+gate output

// ---------------- small helpers ---------------------------------------------
__device__ __forceinline__ float softplus_f(float v){
    return v > 20.f ? v : log1pf(__expf(v));
}
__device__ __forceinline__ float silu_f(float v){
    return v / (1.f + __expf(-v));
}

// ---------------- canvas init: x = mask_token + pos_embed -------------------
__global__ void init_k(const float* __restrict__ mtok, const float* __restrict__ pos){
    int idx = blockIdx.x*256 + threadIdx.x;
    int c = idx % DM;
    int p = (idx / DM) % L_;
    g_x[idx] = mtok[c] + pos[p*DM + c];
}

// ---------------- scatter visible tokens (sorted ids, last-dup wins) --------
__global__ void scatter_k(const float* __restrict__ xv, const int* __restrict__ ids,
                          const float* __restrict__ pos){
    int b = blockIdx.x >> 8;
    int i = blockIdx.x & 255;
    int id = ids[b*256 + i];
    bool last = (i == 255) || (ids[b*256 + i + 1] != id);
    if (!last) return;
    for (int c = threadIdx.x; c < DM; c += blockDim.x)
        g_x[((size_t)b*L_ + id)*DM + c] = xv[((size_t)b*256 + i)*DM + c] + pos[id*DM + c];
}

// ---------------- rmsnorm: one block (256 thr) per row of 512 ---------------
__global__ void rmsnorm_k(const float* __restrict__ x, const float* __restrict__ w,
                          float* __restrict__ o){
    int r = blockIdx.x;
    int t = threadIdx.x;
    const float* xr = x + (size_t)r*DM;
    float v0 = xr[t], v1 = xr[t+256];
    float s = v0*v0 + v1*v1;
    #pragma unroll
    for (int off=16; off; off>>=1) s += __shfl_xor_sync(0xffffffffu, s, off);
    __shared__ float red[8];
    __shared__ float tot;
    if ((t & 31) == 0) red[t>>5] = s;
    __syncthreads();
    if (t < 8){
        float q = red[t];
        #pragma unroll
        for (int off=4; off; off>>=1) q += __shfl_xor_sync(0xffu, q, off);
        if (t == 0) tot = q;
    }
    __syncthreads();
    float rs = rsqrtf(tot * (1.f/DM) + 1e-6f);
    o[(size_t)r*DM + t]       = v0 * rs * w[t];
    o[(size_t)r*DM + t + 256] = v1 * rs * w[t+256];
}

// ---------------- tiled SGEMM, templated; EPI: 0=store 1=accum 2=softplus+bias
template<int BM,int BN,int BK,int TM,int TN,int EPI>
__global__ void sgemm_k(const float* __restrict__ A, const float* __restrict__ W,
                        float* __restrict__ C, int M, int N, int K, int lda,
                        const float* __restrict__ bias){
    __shared__ float As[BK][BM+4];
    __shared__ float Ws[BK][BN+4];
    const int tid = threadIdx.x;
    constexpr int TX = BN/TN;
    const int tx = tid % TX;
    const int ty = tid / TX;
    const int rowBase = blockIdx.y*BM;
    const int colBase = blockIdx.x*BN;

    float acc[TM][TN];
    #pragma unroll
    for (int i=0;i<TM;i++)
        #pragma unroll
        for (int j=0;j<TN;j++) acc[i][j] = 0.f;

    for (int k0=0; k0<K; k0+=BK){
        for (int idx=tid; idx<BM*BK; idx+=256){
            int r = idx / BK, c = idx % BK;
            As[c][r] = A[(size_t)(rowBase+r)*lda + k0 + c];
        }
        for (int idx=tid; idx<BK*BN; idx+=256){
            int r = idx / BN, c = idx % BN;
            Ws[r][c] = W[(size_t)(k0+r)*N + colBase + c];
        }
        __syncthreads();
        #pragma unroll
        for (int kk=0; kk<BK; kk++){
            float ra[TM], rb[TN];
            #pragma unroll
            for (int i=0;i<TM;i+=4) *(float4*)&ra[i] = *(const float4*)&As[kk][ty*TM+i];
            #pragma unroll
            for (int j=0;j<TN;j+=4) *(float4*)&rb[j] = *(const float4*)&Ws[kk][tx*TN+j];
            #pragma unroll
            for (int i=0;i<TM;i++)
                #pragma unroll
                for (int j=0;j<TN;j++)
                    acc[i][j] += ra[i]*rb[j];
        }
        __syncthreads();
    }

    #pragma unroll
    for (int i=0;i<TM;i++){
        int r = rowBase + ty*TM + i;
        #pragma unroll
        for (int j=0;j<TN;j++){
            int c = colBase + tx*TN + j;
            float v = acc[i][j];
            if (EPI == 1)      C[(size_t)r*N + c] += v;
            else if (EPI == 2) C[(size_t)r*N + c] = softplus_f(v + bias[c]);
            else               C[(size_t)r*N + c] = v;
        }
    }
}

// ---------------- causal depthwise conv(4) + bias + SiLU --------------------
__global__ void conv_silu_k(const float* __restrict__ cw, const float* __restrict__ cb){
    int idx = blockIdx.x*256 + threadIdx.x;       // over B*L*DI
    int d  = idx & (DI-1);
    int bt = idx >> 10;                            // b*L + t
    int t  = bt & (L_-1);
    float acc = cb[d];
    #pragma unroll
    for (int k=0;k<4;k++){
        int tt = t - 3 + k;
        if (tt >= 0) acc += g_uz[(size_t)(bt - 3 + k)*(2*DI) + d] * cw[d*4 + k];
    }
    g_u[idx] = silu_f(acc);
}

// ---------------- selective scan + D-skip + SiLU(z) gate --------------------
// block: 256 threads = 16 channels x 16 states. grid: B * (DI/16) = 512 blocks.
__global__ void scan_k(const float* __restrict__ A_log, const float* __restrict__ Dsk){
    int b    = blockIdx.x >> 6;
    int dblk = (blockIdx.x & 63) << 4;
    int ch = threadIdx.x >> 4;
    int s  = threadIdx.x & 15;
    int d  = dblk + ch;

    float a   = -expf(A_log[d*DS + s]);
    float dsk = Dsk[d];
    float h   = 0.f;

    __shared__ float sB[64][16], sC[64][16], sdt[64][16], su[64][16], sz[64][16];

    for (int t0=0; t0<L_; t0+=64){
        for (int idx=threadIdx.x; idx<1024; idx+=256){
            int tt = idx >> 4, j = idx & 15;
            size_t row = (size_t)b*L_ + t0 + tt;
            sB [tt][j] = g_dbc[row*64 + 32 + j];
            sC [tt][j] = g_dbc[row*64 + 48 + j];
            sdt[tt][j] = g_dt[row*DI + dblk + j];
            su [tt][j] = g_u [row*DI + dblk + j];
            sz [tt][j] = g_uz[row*(2*DI) + DI + dblk + j];
        }
        __syncthreads();
        for (int tt=0; tt<64; tt++){
            float dtv = sdt[tt][ch];
            float uv  = su [tt][ch];
            float dA  = __expf(dtv * a);
            h = dA*h + (dtv*uv)*sB[tt][s];
            float p = h * sC[tt][s];
            p += __shfl_xor_sync(0xffffffffu, p, 8);
            p += __shfl_xor_sync(0xffffffffu, p, 4);
            p += __shfl_xor_sync(0xffffffffu, p, 2);
            p += __shfl_xor_sync(0xffffffffu, p, 1);
            if (s == 0){
                float zv = sz[tt][ch];
                g_y[((size_t)b*L_ + t0 + tt)*DI + d] = (p + uv*dsk) * silu_f(zv);
            }
        }
        __syncthreads();
    }
}

// ---------------- head: out[r,p] = xn[r,:] @ head_w + head_b ----------------
__global__ void head_k(const float* __restrict__ hw, const float* __restrict__ hb,
                       float* __restrict__ out){
    int r = blockIdx.x*16 + (threadIdx.x >> 4);
    int p = threadIdx.x & 15;
    const float* xr = g_xn + (size_t)r*DM;
    float acc = 0.f;
    #pragma unroll 4
    for (int k=0;k<DM;k++) acc += xr[k]*hw[k*16 + p];
    out[(size_t)r*16 + p] = acc + hb[p];
}

// ---------------- launch ------------------------------------------------------
extern "C" void kernel_launch(void* const* d_in, const int* in_sizes, int n_in,
                              void* d_out, int out_size){
    const float* x_vis  = (const float*)d_in[0];
    const int*   ids    = (const int*)  d_in[1];
    const float* mtok   = (const float*)d_in[2];
    const float* pos    = (const float*)d_in[3];
    const float* in_w   = (const float*)d_in[4];
    const float* conv_w = (const float*)d_in[5];
    const float* conv_b = (const float*)d_in[6];
    const float* xp_w   = (const float*)d_in[7];
    const float* dt_w   = (const float*)d_in[8];
    const float* dt_b   = (const float*)d_in[9];
    const float* A_log  = (const float*)d_in[10];
    const float* Dsk    = (const float*)d_in[11];
    const float* out_w  = (const float*)d_in[12];
    const float* bn_w   = (const float*)d_in[13];
    const float* n_w    = (const float*)d_in[14];
    const float* h_w    = (const float*)d_in[15];
    const float* h_b    = (const float*)d_in[16];
    float* out = (float*)d_out;

    float *px, *pxn, *puz, *pu, *pdbc, *pdt, *py;
    cudaGetSymbolAddress((void**)&px,  g_x);
    cudaGetSymbolAddress((void**)&pxn, g_xn);
    cudaGetSymbolAddress((void**)&puz, g_uz);
    cudaGetSymbolAddress((void**)&pu,  g_u);
    cudaGetSymbolAddress((void**)&pdbc,g_dbc);
    cudaGetSymbolAddress((void**)&pdt, g_dt);
    cudaGetSymbolAddress((void**)&py,  g_y);

    const int M = B_*L_;   // 8192 rows

    init_k<<<(B_*L_*DM)/256, 256>>>(mtok, pos);
    scatter_k<<<B_*256, 256>>>(x_vis, ids, pos);

    for (int l=0; l<NL; l++){
        const float* inW  = in_w  + (size_t)l*DM*2*DI;
        const float* cW   = conv_w+ (size_t)l*DI*4;
        const float* cB   = conv_b+ (size_t)l*DI;
        const float* xpW  = xp_w  + (size_t)l*DI*64;
        const float* dtW  = dt_w  + (size_t)l*RK*DI;
        const float* dtB  = dt_b  + (size_t)l*DI;
        const float* aL   = A_log + (size_t)l*DI*DS;
        const float* dS   = Dsk   + (size_t)l*DI;
        const float* oW   = out_w + (size_t)l*DI*DM;
        const float* bnW  = bn_w  + (size_t)l*DM;

        rmsnorm_k<<<M, 256>>>(px, bnW, pxn);

        // uz = xn @ in_w : [8192,512] x [512,2048]
        sgemm_k<128,128,16,8,8,0><<<dim3(2*DI/128, M/128), 256>>>(
            pxn, inW, puz, M, 2*DI, DM, DM, nullptr);

        conv_silu_k<<<(M*DI)/256, 256>>>(cW, cB);

        // x_dbl = u @ xp_w : [8192,1024] x [1024,64]
        sgemm_k<64,64,16,4,4,0><<<dim3(1, M/64), 256>>>(
            pu, xpW, pdbc, M, 64, DI, DI, nullptr);

        // dt = softplus(x_dbl[:, :32] @ dt_w + dt_b) : [8192,32(lda 64)] x [32,1024]
        sgemm_k<128,128,16,8,8,2><<<dim3(DI/128, M/128), 256>>>(
            pdbc, dtW, pdt, M, DI, RK, 64, dtB);

        scan_k<<<B_*(DI/16), 256>>>(aL, dS);

        // x += y @ out_w : [8192,1024] x [1024,512], beta=1
        sgemm_k<128,128,16,8,8,1><<<dim3(DM/128, M/128), 256>>>(
            py, oW, px, M, DM, DI, DI, nullptr);
    }

    rmsnorm_k<<<M, 256>>>(px, n_w, pxn);
    head_k<<<M/16, 256>>>(h_w, h_b, out);
}

// round 2
// speedup vs baseline: 1.5778x; 1.5778x over previous
#include <cuda_runtime.h>
#include <math.h>
#include <mma.h>

using namespace nvcuda;

#define B_  8
#define L_  1024
#define DM  512
#define DI  1024
#define DS  16
#define RK  32
#define NL  4

// ---------------- scratch (static device globals: allocation-guard safe) ----
__device__ float g_x  [B_*L_*DM];     // residual stream
__device__ float g_xn [B_*L_*DM];     // rmsnorm output
__device__ float g_uz [B_*L_*2*DI];   // in_proj output (u | z)
__device__ float g_u  [B_*L_*DI];     // conv+silu output
__device__ float g_dbc[B_*L_*64];     // x_proj output (dt_low | B | C)
__device__ float g_dt [B_*L_*DI];     // softplus(dt)
__device__ float g_y  [B_*L_*DI];     // scan+gate output

// ---------------- small helpers ---------------------------------------------
__device__ __forceinline__ float softplus_f(float v){
    return v > 20.f ? v : log1pf(__expf(v));
}
__device__ __forceinline__ float silu_f(float v){
    return v / (1.f + __expf(-v));
}

// ---------------- canvas init: x = mask_token + pos_embed -------------------
__global__ void init_k(const float* __restrict__ mtok, const float* __restrict__ pos){
    int idx = blockIdx.x*256 + threadIdx.x;
    int c = idx % DM;
    int p = (idx / DM) % L_;
    g_x[idx] = mtok[c] + pos[p*DM + c];
}

// ---------------- scatter visible tokens (sorted ids, last-dup wins) --------
__global__ void scatter_k(const float* __restrict__ xv, const int* __restrict__ ids,
                          const float* __restrict__ pos){
    int b = blockIdx.x >> 8;
    int i = blockIdx.x & 255;
    int id = ids[b*256 + i];
    bool last = (i == 255) || (ids[b*256 + i + 1] != id);
    if (!last) return;
    for (int c = threadIdx.x; c < DM; c += blockDim.x)
        g_x[((size_t)b*L_ + id)*DM + c] = xv[((size_t)b*256 + i)*DM + c] + pos[id*DM + c];
}

// ---------------- rmsnorm: one block (256 thr) per row of 512 ---------------
__global__ void rmsnorm_k(const float* __restrict__ x, const float* __restrict__ w,
                          float* __restrict__ o){
    int r = blockIdx.x;
    int t = threadIdx.x;
    const float* xr = x + (size_t)r*DM;
    float v0 = xr[t], v1 = xr[t+256];
    float s = v0*v0 + v1*v1;
    #pragma unroll
    for (int off=16; off; off>>=1) s += __shfl_xor_sync(0xffffffffu, s, off);
    __shared__ float red[8];
    __shared__ float tot;
    if ((t & 31) == 0) red[t>>5] = s;
    __syncthreads();
    if (t < 8){
        float q = red[t];
        #pragma unroll
        for (int off=4; off; off>>=1) q += __shfl_xor_sync(0xffu, q, off);
        if (t == 0) tot = q;
    }
    __syncthreads();
    float rs = rsqrtf(tot * (1.f/DM) + 1e-6f);
    o[(size_t)r*DM + t]       = v0 * rs * w[t];
    o[(size_t)r*DM + t + 256] = v1 * rs * w[t+256];
}

// ---------------- TF32 tensor-core GEMM (wmma m16n16k8) ---------------------
// EPI: 0=store  1=accumulate(+=)  2=softplus(v+bias[c])
template<int BM,int BN,int BK,int WM,int WN,int EPI,int THREADS>
__global__ void __launch_bounds__(THREADS)
tgemm_k(const float* __restrict__ A, const float* __restrict__ W,
        float* __restrict__ C, int M, int N, int K, int lda,
        const float* __restrict__ bias){
    constexpr int WX = BN/WN;          // warps along N
    constexpr int WY = BM/WM;          // warps along M
    constexpr int MI = WM/16;
    constexpr int NI = WN/16;
    constexpr int LDA_S = BK+4;
    constexpr int LDB_S = BN+4;

    __shared__ float As[BM][LDA_S];
    __shared__ float Bs[BK][LDB_S];
    __shared__ float stage[EPI==2 ? WX*WY*256 : 1];

    const int tid  = threadIdx.x;
    const int wid  = tid >> 5;
    const int lane = tid & 31;
    const int wy   = wid / WX;
    const int wx   = wid % WX;
    const int rowBase = blockIdx.y*BM;
    const int colBase = blockIdx.x*BN;

    wmma::fragment<wmma::accumulator,16,16,8,float> acc[MI][NI];
    #pragma unroll
    for (int i=0;i<MI;i++)
        #pragma unroll
        for (int j=0;j<NI;j++)
            wmma::fill_fragment(acc[i][j], 0.f);

    for (int k0=0; k0<K; k0+=BK){
        // stage A tile (convert to tf32 on the way in)
        #pragma unroll
        for (int idx=tid; idx < BM*(BK/4); idx += THREADS){
            int r  = idx / (BK/4);
            int c4 = (idx % (BK/4))*4;
            float4 v = *(const float4*)&A[(size_t)(rowBase+r)*lda + k0 + c4];
            v.x = wmma::__float_to_tf32(v.x);
            v.y = wmma::__float_to_tf32(v.y);
            v.z = wmma::__float_to_tf32(v.z);
            v.w = wmma::__float_to_tf32(v.w);
            *(float4*)&As[r][c4] = v;
        }
        // stage B tile
        #pragma unroll
        for (int idx=tid; idx < BK*(BN/4); idx += THREADS){
            int r  = idx / (BN/4);
            int c4 = (idx % (BN/4))*4;
            float4 v = *(const float4*)&W[(size_t)(k0+r)*N + colBase + c4];
            v.x = wmma::__float_to_tf32(v.x);
            v.y = wmma::__float_to_tf32(v.y);
            v.z = wmma::__float_to_tf32(v.z);
            v.w = wmma::__float_to_tf32(v.w);
            *(float4*)&Bs[r][c4] = v;
        }
        __syncthreads();

        #pragma unroll
        for (int kk=0; kk<BK; kk+=8){
            wmma::fragment<wmma::matrix_a,16,16,8,wmma::precision::tf32,wmma::row_major> af[MI];
            wmma::fragment<wmma::matrix_b,16,16,8,wmma::precision::tf32,wmma::row_major> bf[NI];
            #pragma unroll
            for (int i=0;i<MI;i++)
                wmma::load_matrix_sync(af[i], &As[wy*WM + i*16][kk], LDA_S);
            #pragma unroll
            for (int j=0;j<NI;j++)
                wmma::load_matrix_sync(bf[j], &Bs[kk][wx*WN + j*16], LDB_S);
            #pragma unroll
            for (int i=0;i<MI;i++)
                #pragma unroll
                for (int j=0;j<NI;j++)
                    wmma::mma_sync(acc[i][j], af[i], bf[j], acc[i][j]);
        }
        __syncthreads();
    }

    // epilogue
    #pragma unroll
    for (int i=0;i<MI;i++){
        #pragma unroll
        for (int j=0;j<NI;j++){
            int r0 = rowBase + wy*WM + i*16;
            int c0 = colBase + wx*WN + j*16;
            float* cp = C + (size_t)r0*N + c0;
            if (EPI == 0){
                wmma::store_matrix_sync(cp, acc[i][j], N, wmma::mem_row_major);
            } else if (EPI == 1){
                wmma::fragment<wmma::accumulator,16,16,8,float> cf;
                wmma::load_matrix_sync(cf, cp, N, wmma::mem_row_major);
                #pragma unroll
                for (int e=0;e<cf.num_elements;e++) acc[i][j].x[e] += cf.x[e];
                wmma::store_matrix_sync(cp, acc[i][j], N, wmma::mem_row_major);
            } else {
                float* sp = &stage[wid*256];
                wmma::store_matrix_sync(sp, acc[i][j], 16, wmma::mem_row_major);
                __syncwarp();
                #pragma unroll
                for (int e=lane; e<256; e+=32){
                    int rr = e >> 4, cc = e & 15;
                    C[(size_t)(r0+rr)*N + c0 + cc] =
                        softplus_f(sp[e] + bias[c0+cc]);
                }
                __syncwarp();
            }
        }
    }
}

// ---------------- causal depthwise conv(4) + bias + SiLU --------------------
__global__ void conv_silu_k(const float* __restrict__ cw, const float* __restrict__ cb){
    int idx = blockIdx.x*256 + threadIdx.x;       // over B*L*DI
    int d  = idx & (DI-1);
    int bt = idx >> 10;                            // b*L + t
    int t  = bt & (L_-1);
    float acc = cb[d];
    #pragma unroll
    for (int k=0;k<4;k++){
        int tt = t - 3 + k;
        if (tt >= 0) acc += g_uz[(size_t)(bt - 3 + k)*(2*DI) + d] * cw[d*4 + k];
    }
    g_u[idx] = silu_f(acc);
}

// ---------------- selective scan + D-skip + SiLU(z) gate --------------------
// block: 256 threads = 16 channels x 16 states. grid: B * (DI/16) = 512 blocks.
__global__ void scan_k(const float* __restrict__ A_log, const float* __restrict__ Dsk){
    int b    = blockIdx.x >> 6;
    int dblk = (blockIdx.x & 63) << 4;
    int ch = threadIdx.x >> 4;
    int s  = threadIdx.x & 15;
    int d  = dblk + ch;

    float a   = -expf(A_log[d*DS + s]);
    float dsk = Dsk[d];
    float h   = 0.f;

    __shared__ float sB[64][16], sC[64][16], sdt[64][16], su[64][16], sz[64][16];

    for (int t0=0; t0<L_; t0+=64){
        for (int idx=threadIdx.x; idx<1024; idx+=256){
            int tt = idx >> 4, j = idx & 15;
            size_t row = (size_t)b*L_ + t0 + tt;
            sB [tt][j] = g_dbc[row*64 + 32 + j];
            sC [tt][j] = g_dbc[row*64 + 48 + j];
            sdt[tt][j] = g_dt[row*DI + dblk + j];
            su [tt][j] = g_u [row*DI + dblk + j];
            sz [tt][j] = g_uz[row*(2*DI) + DI + dblk + j];
        }
        __syncthreads();
        for (int tt=0; tt<64; tt++){
            float dtv = sdt[tt][ch];
            float uv  = su [tt][ch];
            float dA  = __expf(dtv * a);
            h = dA*h + (dtv*uv)*sB[tt][s];
            float p = h * sC[tt][s];
            p += __shfl_xor_sync(0xffffffffu, p, 8);
            p += __shfl_xor_sync(0xffffffffu, p, 4);
            p += __shfl_xor_sync(0xffffffffu, p, 2);
            p += __shfl_xor_sync(0xffffffffu, p, 1);
            if (s == 0){
                float zv = sz[tt][ch];
                g_y[((size_t)b*L_ + t0 + tt)*DI + d] = (p + uv*dsk) * silu_f(zv);
            }
        }
        __syncthreads();
    }
}

// ---------------- head: out[r,p] = xn[r,:] @ head_w + head_b ----------------
__global__ void head_k(const float* __restrict__ hw, const float* __restrict__ hb,
                       float* __restrict__ out){
    int r = blockIdx.x*16 + (threadIdx.x >> 4);
    int p = threadIdx.x & 15;
    const float* xr = g_xn + (size_t)r*DM;
    float acc = 0.f;
    #pragma unroll 4
    for (int k=0;k<DM;k++) acc += xr[k]*hw[k*16 + p];
    out[(size_t)r*16 + p] = acc + hb[p];
}

// ---------------- launch ------------------------------------------------------
extern "C" void kernel_launch(void* const* d_in, const int* in_sizes, int n_in,
                              void* d_out, int out_size){
    const float* x_vis  = (const float*)d_in[0];
    const int*   ids    = (const int*)  d_in[1];
    const float* mtok   = (const float*)d_in[2];
    const float* pos    = (const float*)d_in[3];
    const float* in_w   = (const float*)d_in[4];
    const float* conv_w = (const float*)d_in[5];
    const float* conv_b = (const float*)d_in[6];
    const float* xp_w   = (const float*)d_in[7];
    const float* dt_w   = (const float*)d_in[8];
    const float* dt_b   = (const float*)d_in[9];
    const float* A_log  = (const float*)d_in[10];
    const float* Dsk    = (const float*)d_in[11];
    const float* out_w  = (const float*)d_in[12];
    const float* bn_w   = (const float*)d_in[13];
    const float* n_w    = (const float*)d_in[14];
    const float* h_w    = (const float*)d_in[15];
    const float* h_b    = (const float*)d_in[16];
    float* out = (float*)d_out;

    float *px, *pxn, *puz, *pu, *pdbc, *pdt, *py;
    cudaGetSymbolAddress((void**)&px,  g_x);
    cudaGetSymbolAddress((void**)&pxn, g_xn);
    cudaGetSymbolAddress((void**)&puz, g_uz);
    cudaGetSymbolAddress((void**)&pu,  g_u);
    cudaGetSymbolAddress((void**)&pdbc,g_dbc);
    cudaGetSymbolAddress((void**)&pdt, g_dt);
    cudaGetSymbolAddress((void**)&py,  g_y);

    const int M = B_*L_;   // 8192 rows

    init_k<<<(B_*L_*DM)/256, 256>>>(mtok, pos);
    scatter_k<<<B_*256, 256>>>(x_vis, ids, pos);

    for (int l=0; l<NL; l++){
        const float* inW  = in_w  + (size_t)l*DM*2*DI;
        const float* cW   = conv_w+ (size_t)l*DI*4;
        const float* cB   = conv_b+ (size_t)l*DI;
        const float* xpW  = xp_w  + (size_t)l*DI*64;
        const float* dtW  = dt_w  + (size_t)l*RK*DI;
        const float* dtB  = dt_b  + (size_t)l*DI;
        const float* aL   = A_log + (size_t)l*DI*DS;
        const float* dS   = Dsk   + (size_t)l*DI;
        const float* oW   = out_w + (size_t)l*DI*DM;
        const float* bnW  = bn_w  + (size_t)l*DM;

        rmsnorm_k<<<M, 256>>>(px, bnW, pxn);

        // uz = xn @ in_w : [8192,512] x [512,2048]
        tgemm_k<128,128,32,64,32,0,256><<<dim3(2*DI/128, M/128), 256>>>(
            pxn, inW, puz, M, 2*DI, DM, DM, nullptr);

        conv_silu_k<<<(M*DI)/256, 256>>>(cW, cB);

        // x_dbl = u @ xp_w : [8192,1024] x [1024,64]
        tgemm_k<64,64,32,32,32,0,128><<<dim3(1, M/64), 128>>>(
            pu, xpW, pdbc, M, 64, DI, DI, nullptr);

        // dt = softplus(x_dbl[:, :32] @ dt_w + dt_b) : [8192,32(lda 64)] x [32,1024]
        tgemm_k<128,128,32,64,32,2,256><<<dim3(DI/128, M/128), 256>>>(
            pdbc, dtW, pdt, M, DI, RK, 64, dtB);

        scan_k<<<B_*(DI/16), 256>>>(aL, dS);

        // x += y @ out_w : [8192,1024] x [1024,512], beta=1
        tgemm_k<128,128,32,64,32,1,256><<<dim3(DM/128, M/128), 256>>>(
            py, oW, px, M, DM, DI, DI, nullptr);
    }

    rmsnorm_k<<<M, 256>>>(px, n_w, pxn);
    head_k<<<M/16, 256>>>(h_w, h_b, out);
}

// round 3
// speedup vs baseline: 1.6506x; 1.0462x over previous
#include <cuda_runtime.h>
#include <cuda_pipeline.h>
#include <math.h>
#include <mma.h>

using namespace nvcuda;

#define B_  8
#define L_  1024
#define DM  512
#define DI  1024
#define DS  16
#define RK  32
#define NL  4

// ---------------- scratch (static device globals: allocation-guard safe) ----
__device__ float g_x  [B_*L_*DM];     // residual stream
__device__ float g_xn [B_*L_*DM];     // rmsnorm output
__device__ float g_uz [B_*L_*2*DI];   // in_proj output (u | z)
__device__ float g_u  [B_*L_*DI];     // conv+silu output
__device__ float g_dbc[B_*L_*64];     // x_proj output (dt_low | B | C)
__device__ float g_dt [B_*L_*DI];     // softplus(dt)
__device__ float g_y  [B_*L_*DI];     // scan+gate output

// ---------------- small helpers ---------------------------------------------
__device__ __forceinline__ float softplus_f(float v){
    return v > 20.f ? v : log1pf(__expf(v));
}
__device__ __forceinline__ float silu_f(float v){
    return v / (1.f + __expf(-v));
}

// ---------------- canvas init: x = mask_token + pos_embed -------------------
__global__ void init_k(const float* __restrict__ mtok, const float* __restrict__ pos){
    int idx = blockIdx.x*256 + threadIdx.x;
    int c = idx % DM;
    int p = (idx / DM) % L_;
    g_x[idx] = mtok[c] + pos[p*DM + c];
}

// ---------------- scatter visible tokens (sorted ids, last-dup wins) --------
__global__ void scatter_k(const float* __restrict__ xv, const int* __restrict__ ids,
                          const float* __restrict__ pos){
    int b = blockIdx.x >> 8;
    int i = blockIdx.x & 255;
    int id = ids[b*256 + i];
    bool last = (i == 255) || (ids[b*256 + i + 1] != id);
    if (!last) return;
    for (int c = threadIdx.x; c < DM; c += blockDim.x)
        g_x[((size_t)b*L_ + id)*DM + c] = xv[((size_t)b*256 + i)*DM + c] + pos[id*DM + c];
}

// ---------------- rmsnorm: one block (256 thr) per row of 512 ---------------
__global__ void rmsnorm_k(const float* __restrict__ x, const float* __restrict__ w,
                          float* __restrict__ o){
    int r = blockIdx.x;
    int t = threadIdx.x;
    const float* xr = x + (size_t)r*DM;
    float v0 = xr[t], v1 = xr[t+256];
    float s = v0*v0 + v1*v1;
    #pragma unroll
    for (int off=16; off; off>>=1) s += __shfl_xor_sync(0xffffffffu, s, off);
    __shared__ float red[8];
    __shared__ float tot;
    if ((t & 31) == 0) red[t>>5] = s;
    __syncthreads();
    if (t < 8){
        float q = red[t];
        #pragma unroll
        for (int off=4; off; off>>=1) q += __shfl_xor_sync(0xffu, q, off);
        if (t == 0) tot = q;
    }
    __syncthreads();
    float rs = rsqrtf(tot * (1.f/DM) + 1e-6f);
    o[(size_t)r*DM + t]       = v0 * rs * w[t];
    o[(size_t)r*DM + t + 256] = v1 * rs * w[t+256];
}

// ---------------- TF32 tensor-core GEMM, 2-stage cp.async pipeline ----------
// EPI: 0=store  1=accumulate(+=)  2=softplus(v+bias[c])
template<int BM,int BN,int BK,int WM,int WN,int EPI,int THREADS>
__global__ void __launch_bounds__(THREADS)
tgemm_k(const float* __restrict__ A, const float* __restrict__ W,
        float* __restrict__ C, int M, int N, int K, int lda,
        const float* __restrict__ bias){
    constexpr int WX = BN/WN;          // warps along N
    constexpr int WY = BM/WM;          // warps along M
    constexpr int MI = WM/16;
    constexpr int NI = WN/16;
    constexpr int LDA_S = BK+4;        // padded smem strides (16B-aligned)
    constexpr int LDB_S = BN+4;
    constexpr int ASZ = BM*LDA_S;
    constexpr int BSZ = BK*LDB_S;

    extern __shared__ float sm[];
    float* As[2] = { sm,            sm + ASZ };
    float* Bs[2] = { sm + 2*ASZ,    sm + 2*ASZ + BSZ };
    float* stage = sm + 2*ASZ + 2*BSZ;   // EPI==2 only

    const int tid  = threadIdx.x;
    const int wid  = tid >> 5;
    const int lane = tid & 31;
    const int wy   = wid / WX;
    const int wx   = wid % WX;
    const int rowBase = blockIdx.y*BM;
    const int colBase = blockIdx.x*BN;

    wmma::fragment<wmma::accumulator,16,16,8,float> acc[MI][NI];
    #pragma unroll
    for (int i=0;i<MI;i++)
        #pragma unroll
        for (int j=0;j<NI;j++)
            wmma::fill_fragment(acc[i][j], 0.f);

    const int T = K/BK;

    auto prefetch = [&](int t, int buf){
        const int k0 = t*BK;
        #pragma unroll 4
        for (int idx=tid; idx < BM*(BK/4); idx += THREADS){
            int r  = idx / (BK/4);
            int c4 = (idx % (BK/4))*4;
            __pipeline_memcpy_async(&As[buf][r*LDA_S + c4],
                                    &A[(size_t)(rowBase+r)*lda + k0 + c4], 16);
        }
        #pragma unroll 4
        for (int idx=tid; idx < BK*(BN/4); idx += THREADS){
            int r  = idx / (BN/4);
            int c4 = (idx % (BN/4))*4;
            __pipeline_memcpy_async(&Bs[buf][r*LDB_S + c4],
                                    &W[(size_t)(k0+r)*N + colBase + c4], 16);
        }
        __pipeline_commit();
    };

    prefetch(0, 0);

    for (int t=0; t<T; t++){
        const int buf = t & 1;
        if (t+1 < T) prefetch(t+1, buf^1);
        if (t+1 < T) __pipeline_wait_prior(1);
        else         __pipeline_wait_prior(0);
        __syncthreads();

        #pragma unroll
        for (int kk=0; kk<BK; kk+=8){
            wmma::fragment<wmma::matrix_a,16,16,8,wmma::precision::tf32,wmma::row_major> af[MI];
            wmma::fragment<wmma::matrix_b,16,16,8,wmma::precision::tf32,wmma::row_major> bf[NI];
            #pragma unroll
            for (int i=0;i<MI;i++)
                wmma::load_matrix_sync(af[i], &As[buf][(wy*WM + i*16)*LDA_S + kk], LDA_S);
            #pragma unroll
            for (int j=0;j<NI;j++)
                wmma::load_matrix_sync(bf[j], &Bs[buf][kk*LDB_S + wx*WN + j*16], LDB_S);
            #pragma unroll
            for (int i=0;i<MI;i++)
                #pragma unroll
                for (int j=0;j<NI;j++)
                    wmma::mma_sync(acc[i][j], af[i], bf[j], acc[i][j]);
        }
        __syncthreads();
    }

    // epilogue
    #pragma unroll
    for (int i=0;i<MI;i++){
        #pragma unroll
        for (int j=0;j<NI;j++){
            int r0 = rowBase + wy*WM + i*16;
            int c0 = colBase + wx*WN + j*16;
            float* cp = C + (size_t)r0*N + c0;
            if (EPI == 0){
                wmma::store_matrix_sync(cp, acc[i][j], N, wmma::mem_row_major);
            } else if (EPI == 1){
                wmma::fragment<wmma::accumulator,16,16,8,float> cf;
                wmma::load_matrix_sync(cf, cp, N, wmma::mem_row_major);
                #pragma unroll
                for (int e=0;e<cf.num_elements;e++) acc[i][j].x[e] += cf.x[e];
                wmma::store_matrix_sync(cp, acc[i][j], N, wmma::mem_row_major);
            } else {
                float* sp = &stage[wid*256];
                wmma::store_matrix_sync(sp, acc[i][j], 16, wmma::mem_row_major);
                __syncwarp();
                #pragma unroll
                for (int e=lane; e<256; e+=32){
                    int rr = e >> 4, cc = e & 15;
                    C[(size_t)(r0+rr)*N + c0 + cc] =
                        softplus_f(sp[e] + bias[c0+cc]);
                }
                __syncwarp();
            }
        }
    }
}

// ---------------- causal depthwise conv(4) + bias + SiLU --------------------
__global__ void conv_silu_k(const float* __restrict__ cw, const float* __restrict__ cb){
    int idx = blockIdx.x*256 + threadIdx.x;       // over B*L*DI
    int d  = idx & (DI-1);
    int bt = idx >> 10;                            // b*L + t
    int t  = bt & (L_-1);
    float acc = cb[d];
    #pragma unroll
    for (int k=0;k<4;k++){
        int tt = t - 3 + k;
        if (tt >= 0) acc += g_uz[(size_t)(bt - 3 + k)*(2*DI) + d] * cw[d*4 + k];
    }
    g_u[idx] = silu_f(acc);
}

// ---------------- selective scan + D-skip + SiLU(z) gate --------------------
// block: 256 threads = 16 channels x 16 states. grid: B * (DI/16) = 512 blocks.
__global__ void scan_k(const float* __restrict__ A_log, const float* __restrict__ Dsk){
    int b    = blockIdx.x >> 6;
    int dblk = (blockIdx.x & 63) << 4;
    int ch = threadIdx.x >> 4;
    int s  = threadIdx.x & 15;
    int d  = dblk + ch;

    float a   = -expf(A_log[d*DS + s]);
    float dsk = Dsk[d];
    float h   = 0.f;

    __shared__ float sB[64][16], sC[64][16], sdt[64][16], su[64][16], sz[64][16];

    for (int t0=0; t0<L_; t0+=64){
        for (int idx=threadIdx.x; idx<1024; idx+=256){
            int tt = idx >> 4, j = idx & 15;
            size_t row = (size_t)b*L_ + t0 + tt;
            sB [tt][j] = g_dbc[row*64 + 32 + j];
            sC [tt][j] = g_dbc[row*64 + 48 + j];
            sdt[tt][j] = g_dt[row*DI + dblk + j];
            su [tt][j] = g_u [row*DI + dblk + j];
            sz [tt][j] = g_uz[row*(2*DI) + DI + dblk + j];
        }
        __syncthreads();
        for (int tt=0; tt<64; tt++){
            float dtv = sdt[tt][ch];
            float uv  = su [tt][ch];
            float dA  = __expf(dtv * a);
            h = dA*h + (dtv*uv)*sB[tt][s];
            float p = h * sC[tt][s];
            p += __shfl_xor_sync(0xffffffffu, p, 8);
            p += __shfl_xor_sync(0xffffffffu, p, 4);
            p += __shfl_xor_sync(0xffffffffu, p, 2);
            p += __shfl_xor_sync(0xffffffffu, p, 1);
            if (s == 0){
                float zv = sz[tt][ch];
                g_y[((size_t)b*L_ + t0 + tt)*DI + d] = (p + uv*dsk) * silu_f(zv);
            }
        }
        __syncthreads();
    }
}

// ---------------- head: out[r,p] = xn[r,:] @ head_w + head_b ----------------
__global__ void head_k(const float* __restrict__ hw, const float* __restrict__ hb,
                       float* __restrict__ out){
    int r = blockIdx.x*16 + (threadIdx.x >> 4);
    int p = threadIdx.x & 15;
    const float* xr = g_xn + (size_t)r*DM;
    float acc = 0.f;
    #pragma unroll 4
    for (int k=0;k<DM;k++) acc += xr[k]*hw[k*16 + p];
    out[(size_t)r*16 + p] = acc + hb[p];
}

// ---------------- launch ------------------------------------------------------
extern "C" void kernel_launch(void* const* d_in, const int* in_sizes, int n_in,
                              void* d_out, int out_size){
    const float* x_vis  = (const float*)d_in[0];
    const int*   ids    = (const int*)  d_in[1];
    const float* mtok   = (const float*)d_in[2];
    const float* pos    = (const float*)d_in[3];
    const float* in_w   = (const float*)d_in[4];
    const float* conv_w = (const float*)d_in[5];
    const float* conv_b = (const float*)d_in[6];
    const float* xp_w   = (const float*)d_in[7];
    const float* dt_w   = (const float*)d_in[8];
    const float* dt_b   = (const float*)d_in[9];
    const float* A_log  = (const float*)d_in[10];
    const float* Dsk    = (const float*)d_in[11];
    const float* out_w  = (const float*)d_in[12];
    const float* bn_w   = (const float*)d_in[13];
    const float* n_w    = (const float*)d_in[14];
    const float* h_w    = (const float*)d_in[15];
    const float* h_b    = (const float*)d_in[16];
    float* out = (float*)d_out;

    float *px, *pxn, *puz, *pu, *pdbc, *pdt, *py;
    cudaGetSymbolAddress((void**)&px,  g_x);
    cudaGetSymbolAddress((void**)&pxn, g_xn);
    cudaGetSymbolAddress((void**)&puz, g_uz);
    cudaGetSymbolAddress((void**)&pu,  g_u);
    cudaGetSymbolAddress((void**)&pdbc,g_dbc);
    cudaGetSymbolAddress((void**)&pdt, g_dt);
    cudaGetSymbolAddress((void**)&py,  g_y);

    const int M = B_*L_;   // 8192 rows

    // dynamic smem sizes for the big-tile instantiation (128x256, BK=32)
    constexpr int ASZ = 128*36, BSZ = 32*260;
    const int smemBig  = (2*ASZ + 2*BSZ) * 4;               // 103,424 B
    const int smemBig2 = (2*ASZ + 2*BSZ + 16*256) * 4;      // +16KB stage (EPI=2)
    const int smemSml  = (2*(64*36) + 2*(32*68)) * 4;       // 35,840 B

    cudaFuncSetAttribute((const void*)tgemm_k<128,256,32,64,32,0,512>,
                         cudaFuncAttributeMaxDynamicSharedMemorySize, smemBig);
    cudaFuncSetAttribute((const void*)tgemm_k<128,256,32,64,32,1,512>,
                         cudaFuncAttributeMaxDynamicSharedMemorySize, smemBig);
    cudaFuncSetAttribute((const void*)tgemm_k<128,256,32,64,32,2,512>,
                         cudaFuncAttributeMaxDynamicSharedMemorySize, smemBig2);

    init_k<<<(B_*L_*DM)/256, 256>>>(mtok, pos);
    scatter_k<<<B_*256, 256>>>(x_vis, ids, pos);

    for (int l=0; l<NL; l++){
        const float* inW  = in_w  + (size_t)l*DM*2*DI;
        const float* cW   = conv_w+ (size_t)l*DI*4;
        const float* cB   = conv_b+ (size_t)l*DI;
        const float* xpW  = xp_w  + (size_t)l*DI*64;
        const float* dtW  = dt_w  + (size_t)l*RK*DI;
        const float* dtB  = dt_b  + (size_t)l*DI;
        const float* aL   = A_log + (size_t)l*DI*DS;
        const float* dS   = Dsk   + (size_t)l*DI;
        const float* oW   = out_w + (size_t)l*DI*DM;
        const float* bnW  = bn_w  + (size_t)l*DM;

        rmsnorm_k<<<M, 256>>>(px, bnW, pxn);

        // uz = xn @ in_w : [8192,512] x [512,2048]
        tgemm_k<128,256,32,64,32,0,512><<<dim3(2*DI/256, M/128), 512, smemBig>>>(
            pxn, inW, puz, M, 2*DI, DM, DM, nullptr);

        conv_silu_k<<<(M*DI)/256, 256>>>(cW, cB);

        // x_dbl = u @ xp_w : [8192,1024] x [1024,64]
        tgemm_k<64,64,32,32,32,0,128><<<dim3(1, M/64), 128, smemSml>>>(
            pu, xpW, pdbc, M, 64, DI, DI, nullptr);

        // dt = softplus(x_dbl[:, :32] @ dt_w + dt_b) : [8192,32(lda 64)] x [32,1024]
        tgemm_k<128,256,32,64,32,2,512><<<dim3(DI/256, M/128), 512, smemBig2>>>(
            pdbc, dtW, pdt, M, DI, RK, 64, dtB);

        scan_k<<<B_*(DI/16), 256>>>(aL, dS);

        // x += y @ out_w : [8192,1024] x [1024,512], beta=1
        tgemm_k<128,256,32,64,32,1,512><<<dim3(DM/256, M/128), 512, smemBig>>>(
            py, oW, px, M, DM, DI, DI, nullptr);
    }

    rmsnorm_k<<<M, 256>>>(px, n_w, pxn);
    head_k<<<M/16, 256>>>(h_w, h_b, out);
}

// round 5
// speedup vs baseline: 1.6914x; 1.0247x over previous
#include <cuda_runtime.h>
#include <cuda_pipeline.h>
#include <math.h>
#include <mma.h>

using namespace nvcuda;

#define B_  8
#define L_  1024
#define DM  512
#define DI  1024
#define DS  16
#define RK  32
#define NL  4

// ---------------- scratch (static device globals: allocation-guard safe) ----
__device__ float g_x  [B_*L_*DM];     // residual stream
__device__ float g_xn [B_*L_*DM];     // rmsnorm output
__device__ float g_uz [B_*L_*2*DI];   // in_proj output (u | z)
__device__ float g_u  [B_*L_*DI];     // conv+silu output
__device__ float g_dbc[B_*L_*64];     // x_proj output (dt_low | B | C)
__device__ float g_dt [B_*L_*DI];     // softplus(dt)
__device__ float g_y  [B_*L_*DI];     // scan+gate output

// ---------------- small helpers ---------------------------------------------
__device__ __forceinline__ float softplus_f(float v){
    return v > 20.f ? v : log1pf(__expf(v));
}
__device__ __forceinline__ float silu_f(float v){
    return v / (1.f + __expf(-v));
}

// ---------------- canvas init: x = mask_token + pos_embed -------------------
__global__ void init_k(const float* __restrict__ mtok, const float* __restrict__ pos){
    int idx = blockIdx.x*256 + threadIdx.x;
    int c = idx % DM;
    int p = (idx / DM) % L_;
    g_x[idx] = mtok[c] + pos[p*DM + c];
}

// ---------------- scatter visible tokens (sorted ids, last-dup wins) --------
__global__ void scatter_k(const float* __restrict__ xv, const int* __restrict__ ids,
                          const float* __restrict__ pos){
    int b = blockIdx.x >> 8;
    int i = blockIdx.x & 255;
    int id = ids[b*256 + i];
    bool last = (i == 255) || (ids[b*256 + i + 1] != id);
    if (!last) return;
    for (int c = threadIdx.x; c < DM; c += blockDim.x)
        g_x[((size_t)b*L_ + id)*DM + c] = xv[((size_t)b*256 + i)*DM + c] + pos[id*DM + c];
}

// ---------------- rmsnorm: one block (256 thr) per row of 512 ---------------
__global__ void rmsnorm_k(const float* __restrict__ x, const float* __restrict__ w,
                          float* __restrict__ o){
    int r = blockIdx.x;
    int t = threadIdx.x;
    const float* xr = x + (size_t)r*DM;
    float v0 = xr[t], v1 = xr[t+256];
    float s = v0*v0 + v1*v1;
    #pragma unroll
    for (int off=16; off; off>>=1) s += __shfl_xor_sync(0xffffffffu, s, off);
    __shared__ float red[8];
    __shared__ float tot;
    if ((t & 31) == 0) red[t>>5] = s;
    __syncthreads();
    if (t < 8){
        float q = red[t];
        #pragma unroll
        for (int off=4; off; off>>=1) q += __shfl_xor_sync(0xffu, q, off);
        if (t == 0) tot = q;
    }
    __syncthreads();
    float rs = rsqrtf(tot * (1.f/DM) + 1e-6f);
    o[(size_t)r*DM + t]       = v0 * rs * w[t];
    o[(size_t)r*DM + t + 256] = v1 * rs * w[t+256];
}

// ---------------- TF32 wmma GEMM v2: 2 CTA/SM, single sync per K-tile -------
// EPI: 0=store  1=accumulate(+=)  2=softplus(v+bias[c])
template<int BM,int BN,int BK,int WM,int WN,int EPI,int THREADS>
__global__ void __launch_bounds__(THREADS, 2)
tgemm_k(const float* __restrict__ A, const float* __restrict__ W,
        float* __restrict__ C, int M, int N, int K, int lda,
        const float* __restrict__ bias){
    constexpr int WX = BN/WN;          // warps along N
    constexpr int WY = BM/WM;          // warps along M
    constexpr int MI = WM/16;
    constexpr int NI = WN/16;
    constexpr int LDA_S = BK+4;
    constexpr int LDB_S = BN+4;
    constexpr int ASZ = BM*LDA_S;
    constexpr int BSZ = BK*LDB_S;

    extern __shared__ float sm[];
    float* As[2] = { sm,            sm + ASZ };
    float* Bs[2] = { sm + 2*ASZ,    sm + 2*ASZ + BSZ };

    const int tid  = threadIdx.x;
    const int wid  = tid >> 5;
    const int lane = tid & 31;
    const int wy   = wid / WX;
    const int wx   = wid % WX;
    const int rowBase = blockIdx.y*BM;
    const int colBase = blockIdx.x*BN;

    wmma::fragment<wmma::accumulator,16,16,8,float> acc[MI][NI];
    #pragma unroll
    for (int i=0;i<MI;i++)
        #pragma unroll
        for (int j=0;j<NI;j++)
            wmma::fill_fragment(acc[i][j], 0.f);

    const int T = K/BK;

    auto prefetch = [&](int t, int buf){
        const int k0 = t*BK;
        #pragma unroll
        for (int idx=tid; idx < BM*(BK/4); idx += THREADS){
            int r  = idx / (BK/4);
            int c4 = (idx % (BK/4))*4;
            __pipeline_memcpy_async(&As[buf][r*LDA_S + c4],
                                    &A[(size_t)(rowBase+r)*lda + k0 + c4], 16);
        }
        #pragma unroll
        for (int idx=tid; idx < BK*(BN/4); idx += THREADS){
            int r  = idx / (BN/4);
            int c4 = (idx % (BN/4))*4;
            __pipeline_memcpy_async(&Bs[buf][r*LDB_S + c4],
                                    &W[(size_t)(k0+r)*N + colBase + c4], 16);
        }
        __pipeline_commit();
    };

    prefetch(0, 0);

    for (int t=0; t<T; t++){
        const int buf = t & 1;
        __pipeline_wait_prior(0);      // tile t landed
        __syncthreads();               // + all warps done computing tile t-1
        if (t+1 < T) prefetch(t+1, buf^1);   // fills buffer freed by tile t-1

        #pragma unroll
        for (int kk=0; kk<BK; kk+=8){
            wmma::fragment<wmma::matrix_a,16,16,8,wmma::precision::tf32,wmma::row_major> af[MI];
            wmma::fragment<wmma::matrix_b,16,16,8,wmma::precision::tf32,wmma::row_major> bf[NI];
            #pragma unroll
            for (int i=0;i<MI;i++)
                wmma::load_matrix_sync(af[i], &As[buf][(wy*WM + i*16)*LDA_S + kk], LDA_S);
            #pragma unroll
            for (int j=0;j<NI;j++)
                wmma::load_matrix_sync(bf[j], &Bs[buf][kk*LDB_S + wx*WN + j*16], LDB_S);
            #pragma unroll
            for (int i=0;i<MI;i++)
                #pragma unroll
                for (int j=0;j<NI;j++)
                    wmma::mma_sync(acc[i][j], af[i], bf[j], acc[i][j]);
        }
    }

    if (EPI == 2) __syncthreads();     // tiles no longer needed; reuse as stage

    // epilogue
    #pragma unroll
    for (int i=0;i<MI;i++){
        #pragma unroll
        for (int j=0;j<NI;j++){
            int r0 = rowBase + wy*WM + i*16;
            int c0 = colBase + wx*WN + j*16;
            float* cp = C + (size_t)r0*N + c0;
            if (EPI == 0){
                wmma::store_matrix_sync(cp, acc[i][j], N, wmma::mem_row_major);
            } else if (EPI == 1){
                wmma::fragment<wmma::accumulator,16,16,8,float> cf;
                wmma::load_matrix_sync(cf, cp, N, wmma::mem_row_major);
                #pragma unroll
                for (int e=0;e<cf.num_elements;e++) acc[i][j].x[e] += cf.x[e];
                wmma::store_matrix_sync(cp, acc[i][j], N, wmma::mem_row_major);
            } else {
                float* sp = &sm[wid*256];          // alias A-tile region
                wmma::store_matrix_sync(sp, acc[i][j], 16, wmma::mem_row_major);
                __syncwarp();
                #pragma unroll
                for (int e=lane; e<256; e+=32){
                    int rr = e >> 4, cc = e & 15;
                    C[(size_t)(r0+rr)*N + c0 + cc] =
                        softplus_f(sp[e] + bias[c0+cc]);
                }
                __syncwarp();
            }
        }
    }
}

// ---------------- causal depthwise conv(4) + bias + SiLU --------------------
__global__ void conv_silu_k(const float* __restrict__ cw, const float* __restrict__ cb){
    int idx = blockIdx.x*256 + threadIdx.x;       // over B*L*DI
    int d  = idx & (DI-1);
    int bt = idx >> 10;                            // b*L + t
    int t  = bt & (L_-1);
    float acc = cb[d];
    #pragma unroll
    for (int k=0;k<4;k++){
        int tt = t - 3 + k;
        if (tt >= 0) acc += g_uz[(size_t)(bt - 3 + k)*(2*DI) + d] * cw[d*4 + k];
    }
    g_u[idx] = silu_f(acc);
}

// ---------------- selective scan + D-skip + SiLU(z) gate --------------------
// block: 256 threads = 16 channels x 16 states. grid: B * (DI/16) = 512 blocks.
__global__ void scan_k(const float* __restrict__ A_log, const float* __restrict__ Dsk){
    int b    = blockIdx.x >> 6;
    int dblk = (blockIdx.x & 63) << 4;
    int ch = threadIdx.x >> 4;
    int s  = threadIdx.x & 15;
    int d  = dblk + ch;

    float a   = -expf(A_log[d*DS + s]);
    float dsk = Dsk[d];
    float h   = 0.f;

    __shared__ float sB[64][16], sC[64][16], sdt[64][16], su[64][16], sz[64][16];

    for (int t0=0; t0<L_; t0+=64){
        for (int idx=threadIdx.x; idx<1024; idx+=256){
            int tt = idx >> 4, j = idx & 15;
            size_t row = (size_t)b*L_ + t0 + tt;
            sB [tt][j] = g_dbc[row*64 + 32 + j];
            sC [tt][j] = g_dbc[row*64 + 48 + j];
            sdt[tt][j] = g_dt[row*DI + dblk + j];
            su [tt][j] = g_u [row*DI + dblk + j];
            sz [tt][j] = g_uz[row*(2*DI) + DI + dblk + j];
        }
        __syncthreads();
        for (int tt=0; tt<64; tt++){
            float dtv = sdt[tt][ch];
            float uv  = su [tt][ch];
            float dA  = __expf(dtv * a);
            h = dA*h + (dtv*uv)*sB[tt][s];
            float p = h * sC[tt][s];
            p += __shfl_xor_sync(0xffffffffu, p, 8);
            p += __shfl_xor_sync(0xffffffffu, p, 4);
            p += __shfl_xor_sync(0xffffffffu, p, 2);
            p += __shfl_xor_sync(0xffffffffu, p, 1);
            if (s == 0){
                float zv = sz[tt][ch];
                g_y[((size_t)b*L_ + t0 + tt)*DI + d] = (p + uv*dsk) * silu_f(zv);
            }
        }
        __syncthreads();
    }
}

// ---------------- head: out[r,p] = xn[r,:] @ head_w + head_b ----------------
__global__ void head_k(const float* __restrict__ hw, const float* __restrict__ hb,
                       float* __restrict__ out){
    int r = blockIdx.x*16 + (threadIdx.x >> 4);
    int p = threadIdx.x & 15;
    const float* xr = g_xn + (size_t)r*DM;
    float acc = 0.f;
    #pragma unroll 4
    for (int k=0;k<DM;k++) acc += xr[k]*hw[k*16 + p];
    out[(size_t)r*16 + p] = acc + hb[p];
}

// ---------------- launch ------------------------------------------------------
extern "C" void kernel_launch(void* const* d_in, const int* in_sizes, int n_in,
                              void* d_out, int out_size){
    const float* x_vis  = (const float*)d_in[0];
    const int*   ids    = (const int*)  d_in[1];
    const float* mtok   = (const float*)d_in[2];
    const float* pos    = (const float*)d_in[3];
    const float* in_w   = (const float*)d_in[4];
    const float* conv_w = (const float*)d_in[5];
    const float* conv_b = (const float*)d_in[6];
    const float* xp_w   = (const float*)d_in[7];
    const float* dt_w   = (const float*)d_in[8];
    const float* dt_b   = (const float*)d_in[9];
    const float* A_log  = (const float*)d_in[10];
    const float* Dsk    = (const float*)d_in[11];
    const float* out_w  = (const float*)d_in[12];
    const float* bn_w   = (const float*)d_in[13];
    const float* n_w    = (const float*)d_in[14];
    const float* h_w    = (const float*)d_in[15];
    const float* h_b    = (const float*)d_in[16];
    float* out = (float*)d_out;

    float *px, *pxn, *puz, *pu, *pdbc, *pdt, *py;
    cudaGetSymbolAddress((void**)&px,  g_x);
    cudaGetSymbolAddress((void**)&pxn, g_xn);
    cudaGetSymbolAddress((void**)&puz, g_uz);
    cudaGetSymbolAddress((void**)&pu,  g_u);
    cudaGetSymbolAddress((void**)&pdbc,g_dbc);
    cudaGetSymbolAddress((void**)&pdt, g_dt);
    cudaGetSymbolAddress((void**)&py,  g_y);

    const int M = B_*L_;   // 8192 rows

    // smem: 2*(BM*(BK+4) + BK*(BN+4)) floats
    const int smemBig = (2*(128*20 + 16*132)) * 4;   // 37,376 B  (128x128, BK=16)
    const int smemSml = (2*( 64*20 + 16* 68)) * 4;   // 18,944 B  (64x64,  BK=16)

    init_k<<<(B_*L_*DM)/256, 256>>>(mtok, pos);
    scatter_k<<<B_*256, 256>>>(x_vis, ids, pos);

    for (int l=0; l<NL; l++){
        const float* inW  = in_w  + (size_t)l*DM*2*DI;
        const float* cW   = conv_w+ (size_t)l*DI*4;
        const float* cB   = conv_b+ (size_t)l*DI;
        const float* xpW  = xp_w  + (size_t)l*DI*64;
        const float* dtW  = dt_w  + (size_t)l*RK*DI;
        const float* dtB  = dt_b  + (size_t)l*DI;
        const float* aL   = A_log + (size_t)l*DI*DS;
        const float* dS   = Dsk   + (size_t)l*DI;
        const float* oW   = out_w + (size_t)l*DI*DM;
        const float* bnW  = bn_w  + (size_t)l*DM;

        rmsnorm_k<<<M, 256>>>(px, bnW, pxn);

        // uz = xn @ in_w : [8192,512] x [512,2048]
        tgemm_k<128,128,16,32,64,0,256><<<dim3(2*DI/128, M/128), 256, smemBig>>>(
            pxn, inW, puz, M, 2*DI, DM, DM, nullptr);

        conv_silu_k<<<(M*DI)/256, 256>>>(cW, cB);

        // x_dbl = u @ xp_w : [8192,1024] x [1024,64]   (8 warps/block now)
        tgemm_k<64,64,16,16,32,0,256><<<dim3(1, M/64), 256, smemSml>>>(
            pu, xpW, pdbc, M, 64, DI, DI, nullptr);

        // dt = softplus(x_dbl[:, :32] @ dt_w + dt_b) : [8192,32(lda 64)] x [32,1024]
        tgemm_k<128,128,16,32,64,2,256><<<dim3(DI/128, M/128), 256, smemBig>>>(
            pdbc, dtW, pdt, M, DI, RK, 64, dtB);

        scan_k<<<B_*(DI/16), 256>>>(aL, dS);

        // x += y @ out_w : [8192,1024] x [1024,512], beta=1
        tgemm_k<128,128,16,32,64,1,256><<<dim3(DM/128, M/128), 256, smemBig>>>(
            py, oW, px, M, DM, DI, DI, nullptr);
    }

    rmsnorm_k<<<M, 256>>>(px, n_w, pxn);
    head_k<<<M/16, 256>>>(h_w, h_b, out);
}

// round 6
// speedup vs baseline: 1.7346x; 1.0255x over previous
#include <cuda_runtime.h>
#include <cuda_pipeline.h>
#include <math.h>
#include <mma.h>

using namespace nvcuda;

#define B_  8
#define L_  1024
#define DM  512
#define DI  1024
#define DS  16
#define RK  32
#define NL  4

// ---------------- scratch (static device globals: allocation-guard safe) ----
__device__ float g_x  [B_*L_*DM];     // residual stream
__device__ float g_xn [B_*L_*DM];     // rmsnorm output
__device__ float g_uz [B_*L_*2*DI];   // in_proj output (u | z)
__device__ float g_u  [B_*L_*DI];     // conv+silu output
__device__ float g_dbc[B_*L_*64];     // x_proj output (dt_low | B | C)
__device__ float g_y  [B_*L_*DI];     // scan+gate output

// ---------------- small helpers ---------------------------------------------
__device__ __forceinline__ float softplus_f(float v){
    return v > 20.f ? v : log1pf(__expf(v));
}
__device__ __forceinline__ float silu_f(float v){
    return v / (1.f + __expf(-v));
}

// ---------------- canvas init: x = mask_token + pos_embed -------------------
__global__ void init_k(const float* __restrict__ mtok, const float* __restrict__ pos){
    int idx = blockIdx.x*256 + threadIdx.x;
    int c = idx % DM;
    int p = (idx / DM) % L_;
    g_x[idx] = mtok[c] + pos[p*DM + c];
}

// ---------------- scatter visible tokens (sorted ids, last-dup wins) --------
__global__ void scatter_k(const float* __restrict__ xv, const int* __restrict__ ids,
                          const float* __restrict__ pos){
    int b = blockIdx.x >> 8;
    int i = blockIdx.x & 255;
    int id = ids[b*256 + i];
    bool last = (i == 255) || (ids[b*256 + i + 1] != id);
    if (!last) return;
    for (int c = threadIdx.x; c < DM; c += blockDim.x)
        g_x[((size_t)b*L_ + id)*DM + c] = xv[((size_t)b*256 + i)*DM + c] + pos[id*DM + c];
}

// ---------------- rmsnorm: one block (256 thr) per row of 512 ---------------
__global__ void rmsnorm_k(const float* __restrict__ x, const float* __restrict__ w,
                          float* __restrict__ o){
    int r = blockIdx.x;
    int t = threadIdx.x;
    const float* xr = x + (size_t)r*DM;
    float v0 = xr[t], v1 = xr[t+256];
    float s = v0*v0 + v1*v1;
    #pragma unroll
    for (int off=16; off; off>>=1) s += __shfl_xor_sync(0xffffffffu, s, off);
    __shared__ float red[8];
    __shared__ float tot;
    if ((t & 31) == 0) red[t>>5] = s;
    __syncthreads();
    if (t < 8){
        float q = red[t];
        #pragma unroll
        for (int off=4; off; off>>=1) q += __shfl_xor_sync(0xffu, q, off);
        if (t == 0) tot = q;
    }
    __syncthreads();
    float rs = rsqrtf(tot * (1.f/DM) + 1e-6f);
    o[(size_t)r*DM + t]       = v0 * rs * w[t];
    o[(size_t)r*DM + t + 256] = v1 * rs * w[t+256];
}

// ---------------- TF32 wmma GEMM v3: BK=32, 2 CTA/SM, 1 sync per K-tile -----
// EPI: 0=store  1=accumulate(+=)
template<int BM,int BN,int BK,int WM,int WN,int EPI,int THREADS>
__global__ void __launch_bounds__(THREADS, 2)
tgemm_k(const float* __restrict__ A, const float* __restrict__ W,
        float* __restrict__ C, int M, int N, int K, int lda){
    constexpr int WX = BN/WN;
    constexpr int MI = WM/16;
    constexpr int NI = WN/16;
    constexpr int LDA_S = BK+4;
    constexpr int LDB_S = BN+4;
    constexpr int ASZ = BM*LDA_S;
    constexpr int BSZ = BK*LDB_S;

    extern __shared__ float sm[];
    float* As[2] = { sm,            sm + ASZ };
    float* Bs[2] = { sm + 2*ASZ,    sm + 2*ASZ + BSZ };

    const int tid  = threadIdx.x;
    const int wid  = tid >> 5;
    const int wy   = wid / WX;
    const int wx   = wid % WX;
    const int rowBase = blockIdx.y*BM;
    const int colBase = blockIdx.x*BN;

    wmma::fragment<wmma::accumulator,16,16,8,float> acc[MI][NI];
    #pragma unroll
    for (int i=0;i<MI;i++)
        #pragma unroll
        for (int j=0;j<NI;j++)
            wmma::fill_fragment(acc[i][j], 0.f);

    const int T = K/BK;

    auto prefetch = [&](int t, int buf){
        const int k0 = t*BK;
        #pragma unroll
        for (int idx=tid; idx < BM*(BK/4); idx += THREADS){
            int r  = idx / (BK/4);
            int c4 = (idx % (BK/4))*4;
            __pipeline_memcpy_async(&As[buf][r*LDA_S + c4],
                                    &A[(size_t)(rowBase+r)*lda + k0 + c4], 16);
        }
        #pragma unroll
        for (int idx=tid; idx < BK*(BN/4); idx += THREADS){
            int r  = idx / (BN/4);
            int c4 = (idx % (BN/4))*4;
            __pipeline_memcpy_async(&Bs[buf][r*LDB_S + c4],
                                    &W[(size_t)(k0+r)*N + colBase + c4], 16);
        }
        __pipeline_commit();
    };

    prefetch(0, 0);

    for (int t=0; t<T; t++){
        const int buf = t & 1;
        __pipeline_wait_prior(0);      // tile t landed
        __syncthreads();               // all warps done with tile t-1's buffer
        if (t+1 < T) prefetch(t+1, buf^1);

        #pragma unroll
        for (int kk=0; kk<BK; kk+=8){
            wmma::fragment<wmma::matrix_a,16,16,8,wmma::precision::tf32,wmma::row_major> af[MI];
            wmma::fragment<wmma::matrix_b,16,16,8,wmma::precision::tf32,wmma::row_major> bf[NI];
            #pragma unroll
            for (int i=0;i<MI;i++)
                wmma::load_matrix_sync(af[i], &As[buf][(wy*WM + i*16)*LDA_S + kk], LDA_S);
            #pragma unroll
            for (int j=0;j<NI;j++)
                wmma::load_matrix_sync(bf[j], &Bs[buf][kk*LDB_S + wx*WN + j*16], LDB_S);
            #pragma unroll
            for (int i=0;i<MI;i++)
                #pragma unroll
                for (int j=0;j<NI;j++)
                    wmma::mma_sync(acc[i][j], af[i], bf[j], acc[i][j]);
        }
    }

    #pragma unroll
    for (int i=0;i<MI;i++){
        #pragma unroll
        for (int j=0;j<NI;j++){
            int r0 = rowBase + wy*WM + i*16;
            int c0 = colBase + wx*WN + j*16;
            float* cp = C + (size_t)r0*N + c0;
            if (EPI == 0){
                wmma::store_matrix_sync(cp, acc[i][j], N, wmma::mem_row_major);
            } else {
                wmma::fragment<wmma::accumulator,16,16,8,float> cf;
                wmma::load_matrix_sync(cf, cp, N, wmma::mem_row_major);
                #pragma unroll
                for (int e=0;e<cf.num_elements;e++) acc[i][j].x[e] += cf.x[e];
                wmma::store_matrix_sync(cp, acc[i][j], N, wmma::mem_row_major);
            }
        }
    }
}

// ---------------- causal depthwise conv(4) + bias + SiLU --------------------
__global__ void conv_silu_k(const float* __restrict__ cw, const float* __restrict__ cb){
    int idx = blockIdx.x*256 + threadIdx.x;       // over B*L*DI
    int d  = idx & (DI-1);
    int bt = idx >> 10;                            // b*L + t
    int t  = bt & (L_-1);
    float acc = cb[d];
    #pragma unroll
    for (int k=0;k<4;k++){
        int tt = t - 3 + k;
        if (tt >= 0) acc += g_uz[(size_t)(bt - 3 + k)*(2*DI) + d] * cw[d*4 + k];
    }
    g_u[idx] = silu_f(acc);
}

// ---------------- selective scan + fused dt_proj + D-skip + SiLU(z) gate ----
// block: 256 threads = 16 channels x 16 states. grid: B * (DI/16) = 512 blocks.
// dt = softplus(dbc[:, :32] @ dt_w[:, d] + dt_b[d]) computed per chunk in smem.
__global__ void scan_k(const float* __restrict__ A_log, const float* __restrict__ Dsk,
                       const float* __restrict__ dtw,  const float* __restrict__ dtb){
    int b    = blockIdx.x >> 6;
    int dblk = (blockIdx.x & 63) << 4;
    int ch = threadIdx.x >> 4;
    int s  = threadIdx.x & 15;
    int d  = dblk + ch;

    float a   = -expf(A_log[d*DS + s]);
    float dsk = Dsk[d];
    float h   = 0.f;

    __shared__ float swdt[32][17];                 // dt_w block [k][ch]
    __shared__ float sB[64][16], sC[64][16], su[64][16], sz[64][16];
    __shared__ float sdt[64][17];
    __shared__ float slow[64][33];                 // dbc[:, :32] chunk

    for (int i=threadIdx.x; i<32*16; i+=256){
        int k = i >> 4, j = i & 15;
        swdt[k][j] = dtw[k*DI + dblk + j];
    }

    for (int t0=0; t0<L_; t0+=64){
        __syncthreads();
        for (int idx=threadIdx.x; idx<1024; idx+=256){
            int tt = idx >> 4, j = idx & 15;
            size_t row = (size_t)b*L_ + t0 + tt;
            sB [tt][j]    = g_dbc[row*64 + 32 + j];
            sC [tt][j]    = g_dbc[row*64 + 48 + j];
            su [tt][j]    = g_u [row*DI + dblk + j];
            sz [tt][j]    = g_uz[row*(2*DI) + DI + dblk + j];
            slow[tt][j]   = g_dbc[row*64 + j];
            slow[tt][j+16]= g_dbc[row*64 + 16 + j];
        }
        __syncthreads();
        // fused dt_proj: 64x16 outputs, 4 per thread
        for (int idx=threadIdx.x; idx<1024; idx+=256){
            int tt = idx >> 4, j = idx & 15;
            float acc = dtb[dblk + j];
            #pragma unroll
            for (int k=0;k<32;k++) acc += slow[tt][k]*swdt[k][j];
            sdt[tt][j] = softplus_f(acc);
        }
        __syncthreads();
        for (int tt=0; tt<64; tt++){
            float dtv = sdt[tt][ch];
            float uv  = su [tt][ch];
            float dA  = __expf(dtv * a);
            h = dA*h + (dtv*uv)*sB[tt][s];
            float p = h * sC[tt][s];
            p += __shfl_xor_sync(0xffffffffu, p, 8);
            p += __shfl_xor_sync(0xffffffffu, p, 4);
            p += __shfl_xor_sync(0xffffffffu, p, 2);
            p += __shfl_xor_sync(0xffffffffu, p, 1);
            if (s == 0){
                float zv = sz[tt][ch];
                g_y[((size_t)b*L_ + t0 + tt)*DI + d] = (p + uv*dsk) * silu_f(zv);
            }
        }
    }
}

// ---------------- head: out[r,p] = xn[r,:] @ head_w + head_b ----------------
__global__ void head_k(const float* __restrict__ hw, const float* __restrict__ hb,
                       float* __restrict__ out){
    int r = blockIdx.x*16 + (threadIdx.x >> 4);
    int p = threadIdx.x & 15;
    const float* xr = g_xn + (size_t)r*DM;
    float acc = 0.f;
    #pragma unroll 4
    for (int k=0;k<DM;k++) acc += xr[k]*hw[k*16 + p];
    out[(size_t)r*16 + p] = acc + hb[p];
}

// ---------------- launch ------------------------------------------------------
extern "C" void kernel_launch(void* const* d_in, const int* in_sizes, int n_in,
                              void* d_out, int out_size){
    const float* x_vis  = (const float*)d_in[0];
    const int*   ids    = (const int*)  d_in[1];
    const float* mtok   = (const float*)d_in[2];
    const float* pos    = (const float*)d_in[3];
    const float* in_w   = (const float*)d_in[4];
    const float* conv_w = (const float*)d_in[5];
    const float* conv_b = (const float*)d_in[6];
    const float* xp_w   = (const float*)d_in[7];
    const float* dt_w   = (const float*)d_in[8];
    const float* dt_b   = (const float*)d_in[9];
    const float* A_log  = (const float*)d_in[10];
    const float* Dsk    = (const float*)d_in[11];
    const float* out_w  = (const float*)d_in[12];
    const float* bn_w   = (const float*)d_in[13];
    const float* n_w    = (const float*)d_in[14];
    const float* h_w    = (const float*)d_in[15];
    const float* h_b    = (const float*)d_in[16];
    float* out = (float*)d_out;

    float *px, *pxn, *puz, *pu, *pdbc, *py;
    cudaGetSymbolAddress((void**)&px,  g_x);
    cudaGetSymbolAddress((void**)&pxn, g_xn);
    cudaGetSymbolAddress((void**)&puz, g_uz);
    cudaGetSymbolAddress((void**)&pu,  g_u);
    cudaGetSymbolAddress((void**)&pdbc,g_dbc);
    cudaGetSymbolAddress((void**)&py,  g_y);

    const int M = B_*L_;   // 8192 rows

    // smem: 2*(BM*(BK+4) + BK*(BN+4)) floats, BK=32
    const int smemBig = (2*(128*36 + 32*132)) * 4;   // 70,656 B
    const int smemSml = (2*( 64*36 + 32* 68)) * 4;   // 35,840 B

    cudaFuncSetAttribute((const void*)tgemm_k<128,128,32,32,64,0,256>,
        cudaFuncAttributeMaxDynamicSharedMemorySize, smemBig);
    cudaFuncSetAttribute((const void*)tgemm_k<128,128,32,32,64,1,256>,
        cudaFuncAttributeMaxDynamicSharedMemorySize, smemBig);

    init_k<<<(B_*L_*DM)/256, 256>>>(mtok, pos);
    scatter_k<<<B_*256, 256>>>(x_vis, ids, pos);

    for (int l=0; l<NL; l++){
        const float* inW  = in_w  + (size_t)l*DM*2*DI;
        const float* cW   = conv_w+ (size_t)l*DI*4;
        const float* cB   = conv_b+ (size_t)l*DI;
        const float* xpW  = xp_w  + (size_t)l*DI*64;
        const float* dtW  = dt_w  + (size_t)l*RK*DI;
        const float* dtB  = dt_b  + (size_t)l*DI;
        const float* aL   = A_log + (size_t)l*DI*DS;
        const float* dS   = Dsk   + (size_t)l*DI;
        const float* oW   = out_w + (size_t)l*DI*DM;
        const float* bnW  = bn_w  + (size_t)l*DM;

        rmsnorm_k<<<M, 256>>>(px, bnW, pxn);

        // uz = xn @ in_w : [8192,512] x [512,2048]
        tgemm_k<128,128,32,32,64,0,256><<<dim3(2*DI/128, M/128), 256, smemBig>>>(
            pxn, inW, puz, M, 2*DI, DM, DM);

        conv_silu_k<<<(M*DI)/256, 256>>>(cW, cB);

        // x_dbl = u @ xp_w : [8192,1024] x [1024,64]
        tgemm_k<64,64,32,16,32,0,256><<<dim3(1, M/64), 256, smemSml>>>(
            pu, xpW, pdbc, M, 64, DI, DI);

        // scan (fused dt_proj + softplus + gate)
        scan_k<<<B_*(DI/16), 256>>>(aL, dS, dtW, dtB);

        // x += y @ out_w : [8192,1024] x [1024,512], beta=1
        tgemm_k<128,128,32,32,64,1,256><<<dim3(DM/128, M/128), 256, smemBig>>>(
            py, oW, px, M, DM, DI, DI);
    }

    rmsnorm_k<<<M, 256>>>(px, n_w, pxn);
    head_k<<<M/16, 256>>>(h_w, h_b, out);
}